// round 16
// baseline (speedup 1.0000x reference)
#include <cuda_runtime.h>
#include <cuda_fp16.h>
#include <cstdint>

// Problem constants
#define BATCH   4096
#define NTOK    49
#define DIM     256
#define NH      8
#define HD      32
#define MTOK    (BATCH * NTOK)      // 200704
#define QKV_N   (3 * DIM)           // 768
#define KDIM    256
#define SCALE_F 0.17677669529663687f

// Scratch (device globals)
__device__ __half g_w1h[QKV_N * DIM];           // qkv_w^T fp16 [768][256]
__device__ __half g_w2h[DIM * DIM];             // proj_w^T fp16 [256][256]
__device__ __half g_biasf[16 * 7 * 256];        // bias fragment table (57344B)

// fp16 m16n8k16 mma, fp32 accumulate
__device__ __forceinline__ void mma_f16(float c[4], uint32_t a0, uint32_t a1,
                                        uint32_t a2, uint32_t a3,
                                        uint32_t b0, uint32_t b1) {
    asm volatile(
        "mma.sync.aligned.m16n8k16.row.col.f32.f16.f16.f32 "
        "{%0,%1,%2,%3},{%4,%5,%6,%7},{%8,%9},{%0,%1,%2,%3};"
        : "+f"(c[0]), "+f"(c[1]), "+f"(c[2]), "+f"(c[3])
        : "r"(a0), "r"(a1), "r"(a2), "r"(a3), "r"(b0), "r"(b1));
}

__device__ __forceinline__ void cp_async16(void* smem_dst, const void* gptr) {
    uint32_t s = (uint32_t)__cvta_generic_to_shared(smem_dst);
    asm volatile("cp.async.cg.shared.global [%0], [%1], 16;\n" :: "r"(s), "l"(gptr));
}
__device__ __forceinline__ void cp_async4(void* smem_dst, const void* gptr) {
    uint32_t s = (uint32_t)__cvta_generic_to_shared(smem_dst);
    asm volatile("cp.async.ca.shared.global [%0], [%1], 4;\n" :: "r"(s), "l"(gptr));
}
#define CP_COMMIT()  asm volatile("cp.async.commit_group;\n" ::: "memory")
#define CP_WAIT(n)   asm volatile("cp.async.wait_group %0;\n" :: "n"(n) : "memory")

__device__ __forceinline__ uint32_t pack_h2(float a, float b) {
    __half2 h = __floats2half2_rn(a, b);
    return *(uint32_t*)&h;
}

__device__ __forceinline__ void ldsm_x4(uint32_t& r0, uint32_t& r1,
                                        uint32_t& r2, uint32_t& r3,
                                        uint32_t saddr) {
    asm volatile(
        "ldmatrix.sync.aligned.m8n8.x4.shared.b16 {%0,%1,%2,%3}, [%4];"
        : "=r"(r0), "=r"(r1), "=r"(r2), "=r"(r3) : "r"(saddr));
}
__device__ __forceinline__ void ldsm_x4_trans(uint32_t& r0, uint32_t& r1,
                                              uint32_t& r2, uint32_t& r3,
                                              uint32_t saddr) {
    asm volatile(
        "ldmatrix.sync.aligned.m8n8.x4.trans.shared.b16 {%0,%1,%2,%3}, [%4];"
        : "=r"(r0), "=r"(r1), "=r"(r2), "=r"(r3) : "r"(saddr));
}

// ---------------------------------------------------------------------------
// Pre-pass: w1 transpose, w2 transpose, bias FRAGMENT table (validated)
// ---------------------------------------------------------------------------
#define PREP_N1 (DIM * QKV_N)           // 196608
#define PREP_N2 (DIM * DIM)             // 65536
#define PREP_N3 (16 * 7 * 256)          // 28672 halves
#define PREP_TOTAL (PREP_N1 + PREP_N2 + PREP_N3)

__global__ void prep_kernel(const float* __restrict__ qkv_w,
                            const float* __restrict__ proj_w,
                            const float* __restrict__ rpb,
                            __half* __restrict__ w1h, __half* __restrict__ w2h,
                            __half* __restrict__ biasf) {
    int idx = blockIdx.x * 256 + threadIdx.x;
    if (idx < PREP_N1) {
        int r = idx / QKV_N, c = idx - r * QKV_N;
        w1h[c * DIM + r] = __float2half_rn(qkv_w[idx]);
    } else if (idx < PREP_N1 + PREP_N2) {
        int t = idx - PREP_N1;
        int r = t / DIM, c = t - r * DIM;
        w2h[c * DIM + r] = __float2half_rn(proj_w[t]);
    } else if (idx < PREP_TOTAL) {
        int t = idx - PREP_N1 - PREP_N2;
        int hs   = t / 1792;
        int r    = t % 1792;
        int k    = r / 256;
        int r2   = r % 256;
        int lane = r2 / 8;
        int hidx = r2 % 8;
        int e  = 2 * k + (hidx >> 2);
        int s  = hidx & 3;
        int mi = e / 7, nt = e - mi * 7;
        int h  = hs >> 1, sub = hs & 1;
        int g  = lane >> 2, q = lane & 3;
        int i  = sub * 32 + mi * 16 + g + ((s >= 2) ? 8 : 0);
        int j  = nt * 8 + 2 * q + (s & 1);
        float val = 0.f;
        if (i < NTOK && j < NTOK) {
            int ri = i / 7, ci = i - ri * 7;
            int rj = j / 7, cj = j - rj * 7;
            int ridx = (ri - rj + 6) * 13 + (ci - cj + 6);
            val = rpb[ridx * NH + h];
        }
        biasf[t] = __float2half_rn(val);
    }
}

// ---------------------------------------------------------------------------
// MEGAKERNEL v2: per-window QKV GEMM + attention + projection. 512 threads.
// Q seg computed register-direct (accumulator == phase-2 A fragment);
// K/V segs 4x4-tiled (halved A-fragment smem amplification).
// Smem map:
//   XOFF  = 0       : Xh fp16 [64][528]  (x fp16, pad rows zeroed)
//   KOFF  = 33792   : K fp16  [64][528]  (x fp32 STAGED across K+V at load)
//   VOFF  = 67584   : V fp16  [64][528]
//   AOOFF = 101376  : attn-out fp16 [64][576]
//   MOFF  = 138240  : mask fp32 padded [64][224B] (-1e30 pads)
// ---------------------------------------------------------------------------
#define QKV_STRIDE 528
#define XOFF   0
#define KOFF   33792
#define VOFF   67584
#define AOOFF  101376
#define AO_STRIDE 576
#define MOFF   138240
#define MSTRIDE 224
#define FUSE_SMEM (MOFF + 64 * MSTRIDE) // 152576
#define XSTG_STRIDE 1040                // fp32 x staging row stride

__global__ __launch_bounds__(512, 1) void wattn_mega(
    const float* __restrict__ x, const float* __restrict__ mask,
    const float* __restrict__ qkv_b, const __half* __restrict__ biasf,
    const __half* __restrict__ w1, const __half* __restrict__ w2,
    const float* __restrict__ proj_b, float* __restrict__ out)
{
    extern __shared__ __align__(128) char sm[];
    const uint32_t sbase = (uint32_t)__cvta_generic_to_shared(sm);

    const int b    = blockIdx.x;
    const int tid  = threadIdx.x;
    const int lane = tid & 31;
    const int wid  = tid >> 5;
    const int g    = lane >> 2;     // 0..7
    const int q    = lane & 3;      // 0..3
    const int h    = wid >> 1;      // attention head / Q-GEMM column group
    const int sub  = wid & 1;       // attention row half / Q-GEMM row group
    const int hoff = h * 64;

    // ---- Phase 0: async loads — x window (fp32, staged over K+V) + mask
    {
        const float* xsrc = x + (size_t)b * NTOK * DIM;
        for (int idx = tid; idx < NTOK * 64; idx += 512) {
            int tok = idx >> 6, c16 = idx & 63;
            cp_async16(sm + KOFF + tok * XSTG_STRIDE + c16 * 16,
                       xsrc + (size_t)tok * DIM + c16 * 4);
        }
        const float* mrow = mask + (size_t)b * NTOK * NTOK;
        for (int idx = tid; idx < NTOK * NTOK; idx += 512) {
            int i = idx / NTOK, j = idx - i * NTOK;
            cp_async4(sm + MOFF + i * MSTRIDE + j * 4, mrow + idx);
        }
        CP_COMMIT();
    }
    // While loads fly: zero Xh pad rows; fill mask pads with -1e30
    for (int idx = tid; idx < 15 * 132; idx += 512) {
        int r = idx / 132, w = idx - r * 132;
        *(uint32_t*)(sm + XOFF + (NTOK + r) * QKV_STRIDE + w * 4) = 0;
    }
    for (int idx = tid; idx < 64 * 56; idx += 512) {
        int i = idx / 56, j = idx - i * 56;
        if (i >= NTOK || j >= NTOK)
            *(float*)(sm + MOFF + i * MSTRIDE + j * 4) = -1e30f;
    }
    CP_WAIT(0);
    __syncthreads();

    // ---- Phase 0b: convert staged x fp32 -> Xh fp16
    for (int idx = tid; idx < NTOK * 64; idx += 512) {
        int tok = idx >> 6, c16 = idx & 63;
        float4 v = *(const float4*)(sm + KOFF + tok * XSTG_STRIDE + c16 * 16);
        uint2 o;
        o.x = pack_h2(v.x, v.y);
        o.y = pack_h2(v.z, v.w);
        *(uint2*)(sm + XOFF + tok * QKV_STRIDE + c16 * 8) = o;
    }
    __syncthreads();

    // ---- Phase 0c-Q: Q GEMM register-direct. Warp (sub,h): rows sub*32+32,
    //      cols h*32..+32. Accumulator packs straight into phase-2 A frags.
    uint32_t af[2][2][4];
    {
        float cq[2][4][4];
        #pragma unroll
        for (int mi = 0; mi < 2; mi++)
            #pragma unroll
            for (int ni = 0; ni < 4; ni++)
                #pragma unroll
                for (int r = 0; r < 4; r++) cq[mi][ni][r] = 0.f;

        #pragma unroll
        for (int cp = 0; cp < 8; cp++) {
            uint4 ra[2], rb[2];
            #pragma unroll
            for (int mi = 0; mi < 2; mi++) {
                int r0 = sub * 32 + mi * 16 + g;
                ra[mi] = *(const uint4*)(sm + XOFF + r0 * QKV_STRIDE + cp * 64 + q * 16);
                rb[mi] = *(const uint4*)(sm + XOFF + (r0 + 8) * QKV_STRIDE + cp * 64 + q * 16);
            }
            #pragma unroll
            for (int ni = 0; ni < 4; ni++) {
                int n = h * 32 + ni * 8 + g;
                uint4 sb = *(const uint4*)(w1 + (size_t)n * KDIM + cp * 32 + q * 8);
                #pragma unroll
                for (int mi = 0; mi < 2; mi++) {
                    mma_f16(cq[mi][ni], ra[mi].x, rb[mi].x, ra[mi].y, rb[mi].y,
                            sb.x, sb.y);
                    mma_f16(cq[mi][ni], ra[mi].z, rb[mi].z, ra[mi].w, rb[mi].w,
                            sb.z, sb.w);
                }
            }
        }
        // Pack accumulators (+qkv bias) into A fragments (validated identity)
        #pragma unroll
        for (int cc = 0; cc < 2; cc++) {
            int n0 = h * 32 + (2 * cc) * 8 + 2 * q;
            int n1 = h * 32 + (2 * cc + 1) * 8 + 2 * q;
            float2 b0v = *(const float2*)(qkv_b + n0);
            float2 b1v = *(const float2*)(qkv_b + n1);
            #pragma unroll
            for (int mi = 0; mi < 2; mi++) {
                af[mi][cc][0] = pack_h2(cq[mi][2 * cc][0] + b0v.x, cq[mi][2 * cc][1] + b0v.y);
                af[mi][cc][1] = pack_h2(cq[mi][2 * cc][2] + b0v.x, cq[mi][2 * cc][3] + b0v.y);
                af[mi][cc][2] = pack_h2(cq[mi][2 * cc + 1][0] + b1v.x, cq[mi][2 * cc + 1][1] + b1v.y);
                af[mi][cc][3] = pack_h2(cq[mi][2 * cc + 1][2] + b1v.x, cq[mi][2 * cc + 1][3] + b1v.y);
            }
        }
    }

    // ---- Phase 0c-KV: K,V GEMMs, 4x4 warp tiling. Warp (wm4, wcol4):
    //      rows wm4*16..+16, cols wcol4*64..+64.
    {
        const int wm4   = wid & 3;
        const int wcol4 = wid >> 2;     // 0..3
        const int i0 = wm4 * 16 + g;
        const int i1 = i0 + 8;
        #pragma unroll
        for (int seg = 1; seg < 3; seg++) {
            float ck[8][4];
            #pragma unroll
            for (int ni = 0; ni < 8; ni++)
                #pragma unroll
                for (int r = 0; r < 4; r++) ck[ni][r] = 0.f;

            #pragma unroll
            for (int cp = 0; cp < 8; cp++) {
                uint4 ra = *(const uint4*)(sm + XOFF + i0 * QKV_STRIDE + cp * 64 + q * 16 - g * QKV_STRIDE + (i0 - g) * 0 + g * QKV_STRIDE);
                // (simplified below — keep straightforward addressing)
                ra = *(const uint4*)(sm + XOFF + (wm4 * 16 + g) * QKV_STRIDE + cp * 64 + q * 16);
                uint4 rb = *(const uint4*)(sm + XOFF + (wm4 * 16 + g + 8) * QKV_STRIDE + cp * 64 + q * 16);
                #pragma unroll
                for (int ni = 0; ni < 8; ni++) {
                    int n = wcol4 * 64 + ni * 8 + g;
                    uint4 sb = *(const uint4*)(w1 + (size_t)(seg * 256 + n) * KDIM
                                               + cp * 32 + q * 8);
                    mma_f16(ck[ni], ra.x, rb.x, ra.y, rb.y, sb.x, sb.y);
                    mma_f16(ck[ni], ra.z, rb.z, ra.w, rb.w, sb.z, sb.w);
                }
            }
            char* segp = sm + KOFF + (seg - 1) * 33792;
            #pragma unroll
            for (int ni = 0; ni < 8; ni++) {
                int n0 = wcol4 * 64 + ni * 8 + 2 * q;
                float2 bv = *(const float2*)(qkv_b + seg * 256 + n0);
                *(uint32_t*)(segp + i0 * QKV_STRIDE + n0 * 2) =
                    pack_h2(ck[ni][0] + bv.x, ck[ni][1] + bv.y);
                *(uint32_t*)(segp + i1 * QKV_STRIDE + n0 * 2) =
                    pack_h2(ck[ni][2] + bv.x, ck[ni][3] + bv.y);
            }
        }
    }
    __syncthreads();

    // ---- Phase 2: S = Q*K^T (Q fragments already in af registers)
    float c[2][7][4];
    #pragma unroll
    for (int mi = 0; mi < 2; mi++)
        #pragma unroll
        for (int nt = 0; nt < 7; nt++)
            #pragma unroll
            for (int r = 0; r < 4; r++) c[mi][nt][r] = 0.f;

    #pragma unroll
    for (int nt = 0; nt < 7; nt++) {
        uint32_t kaddr = sbase + KOFF + (uint32_t)(nt * 8 + (lane & 7)) * QKV_STRIDE
                       + hoff + ((lane >> 3) * 16);
        uint32_t b0, b1, b2, b3;
        ldsm_x4(b0, b1, b2, b3, kaddr);
        #pragma unroll
        for (int mi = 0; mi < 2; mi++) {
            mma_f16(c[mi][nt], af[mi][0][0], af[mi][0][1],
                    af[mi][0][2], af[mi][0][3], b0, b1);
            mma_f16(c[mi][nt], af[mi][1][0], af[mi][1][1],
                    af[mi][1][2], af[mi][1][3], b2, b3);
        }
    }

    // ---- Phase 3: scale + bias(frag LDG, L1-hot) + padded mask + reg softmax
    const char* bfp = (const char*)biasf + (h * 2 + sub) * 3584 + lane * 16;
    float inv0[2], inv1[2];
    #pragma unroll
    for (int mi = 0; mi < 2; mi++) {
        int i0 = sub * 32 + mi * 16 + g;
        int i1 = i0 + 8;
        const float* m0p = (const float*)(sm + MOFF + i0 * MSTRIDE);
        const float* m1p = (const float*)(sm + MOFF + i1 * MSTRIDE);
        int c0c = (mi * 7) >> 1;        // base chunk: 0 or 3
        uint4 bb[4];
        #pragma unroll
        for (int k = 0; k < 4; k++)
            bb[k] = *(const uint4*)(bfp + (c0c + k) * 512);
        #pragma unroll
        for (int nt = 0; nt < 7; nt++) {
            int e = mi * 7 + nt;
            const uint4& B = bb[(e >> 1) - c0c];
            uint32_t u0 = (e & 1) ? B.z : B.x;
            uint32_t u1 = (e & 1) ? B.w : B.y;
            float2 bf0 = __half22float2(*reinterpret_cast<__half2*>(&u0));
            float2 bf1 = __half22float2(*reinterpret_cast<__half2*>(&u1));
            int j0 = nt * 8 + 2 * q;
            c[mi][nt][0] = c[mi][nt][0] * SCALE_F + bf0.x + m0p[j0];
            c[mi][nt][1] = c[mi][nt][1] * SCALE_F + bf0.y + m0p[j0 + 1];
            c[mi][nt][2] = c[mi][nt][2] * SCALE_F + bf1.x + m1p[j0];
            c[mi][nt][3] = c[mi][nt][3] * SCALE_F + bf1.y + m1p[j0 + 1];
        }
        float m0 = -1e30f, m1 = -1e30f;
        #pragma unroll
        for (int nt = 0; nt < 7; nt++) {
            m0 = fmaxf(m0, fmaxf(c[mi][nt][0], c[mi][nt][1]));
            m1 = fmaxf(m1, fmaxf(c[mi][nt][2], c[mi][nt][3]));
        }
        m0 = fmaxf(m0, __shfl_xor_sync(0xffffffffu, m0, 1));
        m0 = fmaxf(m0, __shfl_xor_sync(0xffffffffu, m0, 2));
        m1 = fmaxf(m1, __shfl_xor_sync(0xffffffffu, m1, 1));
        m1 = fmaxf(m1, __shfl_xor_sync(0xffffffffu, m1, 2));
        float s0 = 0.f, s1 = 0.f;
        #pragma unroll
        for (int nt = 0; nt < 7; nt++) {
            c[mi][nt][0] = __expf(c[mi][nt][0] - m0); s0 += c[mi][nt][0];
            c[mi][nt][1] = __expf(c[mi][nt][1] - m0); s0 += c[mi][nt][1];
            c[mi][nt][2] = __expf(c[mi][nt][2] - m1); s1 += c[mi][nt][2];
            c[mi][nt][3] = __expf(c[mi][nt][3] - m1); s1 += c[mi][nt][3];
        }
        s0 += __shfl_xor_sync(0xffffffffu, s0, 1);
        s0 += __shfl_xor_sync(0xffffffffu, s0, 2);
        s1 += __shfl_xor_sync(0xffffffffu, s1, 1);
        s1 += __shfl_xor_sync(0xffffffffu, s1, 2);
        inv0[mi] = 1.f / s0;
        inv1[mi] = 1.f / s1;
    }

    // ---- Pack P into fp16 A-fragments (registers only)
    uint32_t pa[2][4][4];
    #pragma unroll
    for (int mi = 0; mi < 2; mi++) {
        #pragma unroll
        for (int ch = 0; ch < 4; ch++) {
            int nt0 = 2 * ch, nt1 = 2 * ch + 1;
            pa[mi][ch][0] = pack_h2(c[mi][nt0][0] * inv0[mi], c[mi][nt0][1] * inv0[mi]);
            pa[mi][ch][1] = pack_h2(c[mi][nt0][2] * inv1[mi], c[mi][nt0][3] * inv1[mi]);
            if (nt1 < 7) {
                pa[mi][ch][2] = pack_h2(c[mi][nt1][0] * inv0[mi], c[mi][nt1][1] * inv0[mi]);
                pa[mi][ch][3] = pack_h2(c[mi][nt1][2] * inv1[mi], c[mi][nt1][3] * inv1[mi]);
            } else {
                pa[mi][ch][2] = 0u;
                pa[mi][ch][3] = 0u;
            }
        }
    }

    // ---- Phase 4: PV mma; B-frags via ldmatrix.trans on V region
    #pragma unroll
    for (int mi = 0; mi < 2; mi++) {
        int i0 = sub * 32 + mi * 16 + g;
        int i1 = i0 + 8;
        #pragma unroll
        for (int ni = 0; ni < 4; ni++) {
            float o[4] = {0.f, 0.f, 0.f, 0.f};
            #pragma unroll
            for (int hf = 0; hf < 2; hf++) {
                uint32_t addr = sbase + VOFF + (uint32_t)(hf * 32 + lane) * QKV_STRIDE
                              + hoff + ni * 16;
                uint32_t r0, r1, r2, r3;
                ldsm_x4_trans(r0, r1, r2, r3, addr);
                mma_f16(o, pa[mi][2 * hf][0], pa[mi][2 * hf][1],
                        pa[mi][2 * hf][2], pa[mi][2 * hf][3], r0, r1);
                mma_f16(o, pa[mi][2 * hf + 1][0], pa[mi][2 * hf + 1][1],
                        pa[mi][2 * hf + 1][2], pa[mi][2 * hf + 1][3], r2, r3);
            }
            int colb = (h * 32 + ni * 8) * 2 + q * 4;
            *(uint32_t*)(sm + AOOFF + i0 * AO_STRIDE + colb) = pack_h2(o[0], o[1]);
            *(uint32_t*)(sm + AOOFF + i1 * AO_STRIDE + colb) = pack_h2(o[2], o[3]);
        }
    }
    __syncthreads();

    // ---- Phase 5: proj GEMM [64x256] = AO[64x256] x W2T[256x256]^T
    const int wm   = wid & 1;
    const int wcol = wid >> 1;         // 0..7
    float d[2][4][4];
    #pragma unroll
    for (int mi = 0; mi < 2; mi++)
        #pragma unroll
        for (int ni = 0; ni < 4; ni++)
            #pragma unroll
            for (int r = 0; r < 4; r++) d[mi][ni][r] = 0.f;

    #pragma unroll
    for (int cp = 0; cp < 8; cp++) {
        uint4 ra[2], rb[2];
        #pragma unroll
        for (int mi = 0; mi < 2; mi++) {
            int r0 = wm * 32 + mi * 16 + g;
            ra[mi] = *(const uint4*)(sm + AOOFF + r0 * AO_STRIDE + cp * 64 + q * 16);
            rb[mi] = *(const uint4*)(sm + AOOFF + (r0 + 8) * AO_STRIDE + cp * 64 + q * 16);
        }
        #pragma unroll
        for (int ni = 0; ni < 4; ni++) {
            int n = wcol * 32 + ni * 8 + g;
            uint4 sb = *(const uint4*)(w2 + (size_t)n * KDIM + cp * 32 + q * 8);
            #pragma unroll
            for (int mi = 0; mi < 2; mi++) {
                mma_f16(d[mi][ni], ra[mi].x, rb[mi].x, ra[mi].y, rb[mi].y, sb.x, sb.y);
                mma_f16(d[mi][ni], ra[mi].z, rb[mi].z, ra[mi].w, rb[mi].w, sb.z, sb.w);
            }
        }
    }

    // ---- Epilogue: + proj_b, fp32 out (valid rows only)
    #pragma unroll
    for (int mi = 0; mi < 2; mi++) {
        int i0 = wm * 32 + mi * 16 + g;
        int i1 = i0 + 8;
        #pragma unroll
        for (int ni = 0; ni < 4; ni++) {
            int n0 = wcol * 32 + ni * 8 + 2 * q;
            float2 pb = *(const float2*)(proj_b + n0);
            if (i0 < NTOK) {
                float2 v = make_float2(d[mi][ni][0] + pb.x, d[mi][ni][1] + pb.y);
                *(float2*)(out + ((size_t)b * NTOK + i0) * DIM + n0) = v;
            }
            if (i1 < NTOK) {
                float2 v = make_float2(d[mi][ni][2] + pb.x, d[mi][ni][3] + pb.y);
                *(float2*)(out + ((size_t)b * NTOK + i1) * DIM + n0) = v;
            }
        }
    }
}

// ---------------------------------------------------------------------------
extern "C" void kernel_launch(void* const* d_in, const int* in_sizes, int n_in,
                              void* d_out, int out_size)
{
    const float* x      = (const float*)d_in[0];
    const float* mask   = (const float*)d_in[1];
    const float* qkv_w  = (const float*)d_in[2];
    const float* qkv_b  = (const float*)d_in[3];
    const float* rpb    = (const float*)d_in[4];
    const float* proj_w = (const float*)d_in[5];
    const float* proj_b = (const float*)d_in[6];
    float* out = (float*)d_out;

    __half *w1h, *w2h, *biasf;
    cudaGetSymbolAddress((void**)&w1h, g_w1h);
    cudaGetSymbolAddress((void**)&w2h, g_w2h);
    cudaGetSymbolAddress((void**)&biasf, g_biasf);

    cudaFuncSetAttribute(wattn_mega,
                         cudaFuncAttributeMaxDynamicSharedMemorySize, FUSE_SMEM);

    // 0) Pre-pass (weights transpose + bias fragment table)
    prep_kernel<<<(PREP_TOTAL + 255) / 256, 256>>>(qkv_w, proj_w, rpb,
                                                   w1h, w2h, biasf);

    // 1) Megakernel: QKV GEMM + attention + projection per window
    wattn_mega<<<BATCH, 512, FUSE_SMEM>>>(
        x, mask, qkv_b, biasf, w1h, w2h, proj_b, out);
}

// round 17
// speedup vs baseline: 1.1228x; 1.1228x over previous
#include <cuda_runtime.h>
#include <cuda_fp16.h>
#include <cstdint>

// Problem constants
#define BATCH   4096
#define NTOK    49
#define DIM     256
#define NH      8
#define HD      32
#define MTOK    (BATCH * NTOK)      // 200704
#define QKV_N   (3 * DIM)           // 768
#define KDIM    256
#define SCALE_F 0.17677669529663687f

// Scratch (device globals)
__device__ __half g_xh[(size_t)MTOK * DIM];     // x in fp16
__device__ __half g_qkvh[(size_t)MTOK * QKV_N]; // qkv in fp16 (308 MB)
__device__ __half g_w1h[QKV_N * DIM];           // qkv_w^T fp16 [768][256]
__device__ __half g_w2h[DIM * DIM];             // proj_w^T fp16 [256][256]
__device__ __half g_biasf[16 * 7 * 256];        // bias fragment table (57344B)

// fp16 m16n8k16 mma, fp32 accumulate
__device__ __forceinline__ void mma_f16(float c[4], uint32_t a0, uint32_t a1,
                                        uint32_t a2, uint32_t a3,
                                        uint32_t b0, uint32_t b1) {
    asm volatile(
        "mma.sync.aligned.m16n8k16.row.col.f32.f16.f16.f32 "
        "{%0,%1,%2,%3},{%4,%5,%6,%7},{%8,%9},{%0,%1,%2,%3};"
        : "+f"(c[0]), "+f"(c[1]), "+f"(c[2]), "+f"(c[3])
        : "r"(a0), "r"(a1), "r"(a2), "r"(a3), "r"(b0), "r"(b1));
}

__device__ __forceinline__ void cp_async16(void* smem_dst, const void* gptr) {
    uint32_t s = (uint32_t)__cvta_generic_to_shared(smem_dst);
    asm volatile("cp.async.cg.shared.global [%0], [%1], 16;\n" :: "r"(s), "l"(gptr));
}
__device__ __forceinline__ void cp_async4(void* smem_dst, const void* gptr) {
    uint32_t s = (uint32_t)__cvta_generic_to_shared(smem_dst);
    asm volatile("cp.async.ca.shared.global [%0], [%1], 4;\n" :: "r"(s), "l"(gptr));
}
#define CP_COMMIT()  asm volatile("cp.async.commit_group;\n" ::: "memory")
#define CP_WAIT(n)   asm volatile("cp.async.wait_group %0;\n" :: "n"(n) : "memory")

__device__ __forceinline__ uint32_t pack_h2(float a, float b) {
    __half2 h = __floats2half2_rn(a, b);
    return *(uint32_t*)&h;
}

__device__ __forceinline__ void ldsm_x4(uint32_t& r0, uint32_t& r1,
                                        uint32_t& r2, uint32_t& r3,
                                        uint32_t saddr) {
    asm volatile(
        "ldmatrix.sync.aligned.m8n8.x4.shared.b16 {%0,%1,%2,%3}, [%4];"
        : "=r"(r0), "=r"(r1), "=r"(r2), "=r"(r3) : "r"(saddr));
}
__device__ __forceinline__ void ldsm_x4_trans(uint32_t& r0, uint32_t& r1,
                                              uint32_t& r2, uint32_t& r3,
                                              uint32_t saddr) {
    asm volatile(
        "ldmatrix.sync.aligned.m8n8.x4.trans.shared.b16 {%0,%1,%2,%3}, [%4];"
        : "=r"(r0), "=r"(r1), "=r"(r2), "=r"(r3) : "r"(saddr));
}

// ---------------------------------------------------------------------------
// Merged pre-pass: x->fp16 (bulk), w1 transpose, w2 transpose, bias fragments
// ---------------------------------------------------------------------------
#define PREP_N0 (MTOK * DIM / 4)        // 12845056 float4s (f2h)
#define PREP_N1 (DIM * QKV_N)           // 196608
#define PREP_N2 (DIM * DIM)             // 65536
#define PREP_N3 (16 * 7 * 256)          // 28672 halves
#define PREP_TOTAL (PREP_N0 + PREP_N1 + PREP_N2 + PREP_N3)

__global__ void prep_kernel(const float* __restrict__ x, __half* __restrict__ xh,
                            const float* __restrict__ qkv_w,
                            const float* __restrict__ proj_w,
                            const float* __restrict__ rpb,
                            __half* __restrict__ w1h, __half* __restrict__ w2h,
                            __half* __restrict__ biasf) {
    int idx = blockIdx.x * 256 + threadIdx.x;
    if (idx < PREP_N0) {
        float4 v = ((const float4*)x)[idx];
        __half2* o = (__half2*)xh;
        o[2 * idx]     = __floats2half2_rn(v.x, v.y);
        o[2 * idx + 1] = __floats2half2_rn(v.z, v.w);
    } else if (idx < PREP_N0 + PREP_N1) {
        int t = idx - PREP_N0;
        int r = t / QKV_N, c = t - r * QKV_N;
        w1h[c * DIM + r] = __float2half_rn(qkv_w[t]);
    } else if (idx < PREP_N0 + PREP_N1 + PREP_N2) {
        int t = idx - PREP_N0 - PREP_N1;
        int r = t / DIM, c = t - r * DIM;
        w2h[c * DIM + r] = __float2half_rn(proj_w[t]);
    } else if (idx < PREP_TOTAL) {
        int t = idx - PREP_N0 - PREP_N1 - PREP_N2;
        int hs   = t / 1792;
        int r    = t % 1792;
        int k    = r / 256;
        int r2   = r % 256;
        int lane = r2 / 8;
        int hidx = r2 % 8;
        int e  = 2 * k + (hidx >> 2);
        int s  = hidx & 3;
        int mi = e / 7, nt = e - mi * 7;
        int h  = hs >> 1, sub = hs & 1;
        int g  = lane >> 2, q = lane & 3;
        int i  = sub * 32 + mi * 16 + g + ((s >= 2) ? 8 : 0);
        int j  = nt * 8 + 2 * q + (s & 1);
        float val = 0.f;
        if (i < NTOK && j < NTOK) {
            int ri = i / 7, ci = i - ri * 7;
            int rj = j / 7, cj = j - rj * 7;
            int ridx = (ri - rj + 6) * 13 + (ci - cj + 6);
            val = rpb[ridx * NH + h];
        }
        biasf[t] = __float2half_rn(val);
    }
}

// ---------------------------------------------------------------------------
// FP16 QKV GEMM (R9/R14 proven form, unchanged)
// ---------------------------------------------------------------------------
#define BKH 32
#define TILE_BYTES (128 * 64)
#define STAGE_BYTES (2 * TILE_BYTES)
#define HSTAGES 4
#define GEMM_SMEM_H (HSTAGES * STAGE_BYTES)

__global__ __launch_bounds__(256, 2) void gemm_h(
    const __half* __restrict__ A, const __half* __restrict__ BT,
    const float* __restrict__ bias, __half* __restrict__ C, int N)
{
    extern __shared__ __align__(128) char smem[];

    const int tid  = threadIdx.x;
    const int lane = tid & 31;
    const int warp = tid >> 5;
    const int wm   = warp & 1;
    const int wn   = warp >> 1;
    const int bm   = blockIdx.y * 128;
    const int bn   = blockIdx.x * 128;
    const int tig  = lane & 3;
    const int grp  = lane >> 2;

    float c[4][4][4];
    #pragma unroll
    for (int mi = 0; mi < 4; mi++)
        #pragma unroll
        for (int ni = 0; ni < 4; ni++)
            #pragma unroll
            for (int r = 0; r < 4; r++) c[mi][ni][r] = 0.f;

    auto load_stage = [&](int slot, int kt) {
        char* ab = smem + slot * STAGE_BYTES;
        char* bb = ab + TILE_BYTES;
        const __half* ag = A  + (size_t)bm * KDIM + kt * BKH;
        const __half* bg = BT + (size_t)bn * KDIM + kt * BKH;
        #pragma unroll
        for (int j = 0; j < 2; j++) {
            int sgi = tid + j * 256;
            int r   = sgi >> 2;
            int cc  = sgi & 3;
            cp_async16(ab + r * 64 + cc * 16, ag + (size_t)r * KDIM + cc * 8);
            cp_async16(bb + r * 64 + cc * 16, bg + (size_t)r * KDIM + cc * 8);
        }
    };

    const int ITERS = KDIM / BKH;
    #pragma unroll
    for (int p = 0; p < HSTAGES - 1; p++) { load_stage(p, p); CP_COMMIT(); }

    for (int it = 0; it < ITERS; it++) {
        CP_WAIT(HSTAGES - 2);
        __syncthreads();

        int nk = it + HSTAGES - 1;
        if (nk < ITERS) load_stage(nk & (HSTAGES - 1), nk);
        CP_COMMIT();

        const char* as = smem + (it & (HSTAGES - 1)) * STAGE_BYTES;
        const char* bs = as + TILE_BYTES;

        uint4 ra[4], rb[4];
        #pragma unroll
        for (int mi = 0; mi < 4; mi++) {
            int row = wm * 64 + mi * 16 + grp;
            ra[mi] = *(const uint4*)(as + row * 64 + tig * 16);
            rb[mi] = *(const uint4*)(as + (row + 8) * 64 + tig * 16);
        }
        #pragma unroll
        for (int ni = 0; ni < 4; ni++) {
            int col = wn * 32 + ni * 8 + grp;
            uint4 sb = *(const uint4*)(bs + col * 64 + tig * 16);
            #pragma unroll
            for (int mi = 0; mi < 4; mi++) {
                mma_f16(c[mi][ni], ra[mi].x, rb[mi].x, ra[mi].y, rb[mi].y, sb.x, sb.y);
                mma_f16(c[mi][ni], ra[mi].z, rb[mi].z, ra[mi].w, rb[mi].w, sb.z, sb.w);
            }
        }
    }

    #pragma unroll
    for (int mi = 0; mi < 4; mi++) {
        int row0 = bm + wm * 64 + mi * 16 + grp;
        #pragma unroll
        for (int ni = 0; ni < 4; ni++) {
            int col0 = bn + wn * 32 + ni * 8 + tig * 2;
            float bi0 = bias[col0], bi1 = bias[col0 + 1];
            *(__half2*)(C + (size_t)row0 * N + col0) =
                __floats2half2_rn(c[mi][ni][0] + bi0, c[mi][ni][1] + bi1);
            *(__half2*)(C + (size_t)(row0 + 8) * N + col0) =
                __floats2half2_rn(c[mi][ni][2] + bi0, c[mi][ni][3] + bi1);
        }
    }
}

// ---------------------------------------------------------------------------
// Fused attention + projection (R14 skeleton; phase-1 loops div/mod-free)
// ---------------------------------------------------------------------------
#define QKV_STRIDE 528
#define REG_BYTES  (64 * QKV_STRIDE)    // 33792 per region
#define QOFF   0
#define KOFF   REG_BYTES
#define VOFF   (2 * REG_BYTES)
#define AOOFF  (3 * REG_BYTES)          // 101376
#define AO_STRIDE 576
#define MOFF   (AOOFF + 64 * AO_STRIDE) // 138240
#define MSTRIDE 224                     // 56 floats per padded mask row
#define FUSE_SMEM (MOFF + 64 * MSTRIDE) // 152576

__global__ __launch_bounds__(512, 1) void attn_proj_fused(
    const __half* __restrict__ qkv, const float* __restrict__ mask,
    const __half* __restrict__ biasf, const __half* __restrict__ w2,
    const float* __restrict__ proj_b, float* __restrict__ out)
{
    extern __shared__ __align__(128) char sm[];
    const uint32_t sbase = (uint32_t)__cvta_generic_to_shared(sm);

    const int b    = blockIdx.x;
    const int tid  = threadIdx.x;
    const int lane = tid & 31;
    const int wid  = tid >> 5;
    const int g    = lane >> 2;     // 0..7
    const int q    = lane & 3;      // 0..3

    // ---- Phase 1: async loads, all index math div/mod-free
    {
        const __half* src = qkv + (size_t)b * NTOK * QKV_N;
        for (int tok = wid; tok < NTOK; tok += 16) {
            const __half* srow = src + (size_t)tok * QKV_N;
            char* drow = sm + tok * QKV_STRIDE;
            #pragma unroll
            for (int c16 = lane; c16 < 96; c16 += 32) {
                int seg = c16 >> 5;
                int off = (c16 & 31) * 16;
                cp_async16(drow + seg * REG_BYTES + off, srow + c16 * 8);
            }
        }
        const float* mrow = mask + (size_t)b * NTOK * NTOK;
        for (int i = wid; i < NTOK; i += 16) {
            const float* msrc = mrow + i * NTOK;
            char* mdst = sm + MOFF + i * MSTRIDE;
            #pragma unroll
            for (int j = lane; j < NTOK; j += 32)
                cp_async4(mdst + j * 4, msrc + j);
        }
        CP_COMMIT();
    }
    // While loads fly: zero Q/K/V pad rows; fill mask pads with -1e30
    #pragma unroll
    for (int reg = 0; reg < 3; reg++) {
        if (wid < 15) {
            char* prow = sm + reg * REG_BYTES + (NTOK + wid) * QKV_STRIDE;
            #pragma unroll
            for (int w = lane; w < 132; w += 32)
                *(uint32_t*)(prow + w * 4) = 0;
        }
    }
    for (int i = wid; i < 64; i += 16) {
        char* mdst = sm + MOFF + i * MSTRIDE;
        int j0 = (i < NTOK) ? NTOK : 0;
        for (int j = j0 + lane; j < 56; j += 32)
            *(float*)(mdst + j * 4) = -1e30f;
    }
    CP_WAIT(0);
    __syncthreads();

    // ---- Phase 2: S = Q*K^T per warp (head h, rows [sub*32, sub*32+32))
    const int h   = wid >> 1;
    const int sub = wid & 1;
    const int hoff = h * 64;

    float c[2][7][4];
    #pragma unroll
    for (int mi = 0; mi < 2; mi++)
        #pragma unroll
        for (int nt = 0; nt < 7; nt++)
            #pragma unroll
            for (int r = 0; r < 4; r++) c[mi][nt][r] = 0.f;

    uint32_t afr[2][2][4];
    #pragma unroll
    for (int mi = 0; mi < 2; mi++) {
        int r0 = sub * 32 + mi * 16;
        #pragma unroll
        for (int cc = 0; cc < 2; cc++) {
            uint32_t addr = sbase + QOFF + (uint32_t)(r0 + (lane & 15)) * QKV_STRIDE
                          + hoff + cc * 32 + ((lane >> 4) * 16);
            ldsm_x4(afr[mi][cc][0], afr[mi][cc][1], afr[mi][cc][2], afr[mi][cc][3], addr);
        }
    }
    #pragma unroll
    for (int nt = 0; nt < 7; nt++) {
        uint32_t kaddr = sbase + KOFF + (uint32_t)(nt * 8 + (lane & 7)) * QKV_STRIDE
                       + hoff + ((lane >> 3) * 16);
        uint32_t b0, b1, b2, b3;
        ldsm_x4(b0, b1, b2, b3, kaddr);
        #pragma unroll
        for (int mi = 0; mi < 2; mi++) {
            mma_f16(c[mi][nt], afr[mi][0][0], afr[mi][0][1],
                    afr[mi][0][2], afr[mi][0][3], b0, b1);
            mma_f16(c[mi][nt], afr[mi][1][0], afr[mi][1][1],
                    afr[mi][1][2], afr[mi][1][3], b2, b3);
        }
    }

    // ---- Phase 3: scale + bias(frag LDG, L1-hot) + padded mask + reg softmax
    const char* bfp = (const char*)biasf + (h * 2 + sub) * 3584 + lane * 16;
    float inv0[2], inv1[2];
    #pragma unroll
    for (int mi = 0; mi < 2; mi++) {
        int i0 = sub * 32 + mi * 16 + g;
        int i1 = i0 + 8;
        const float* m0p = (const float*)(sm + MOFF + i0 * MSTRIDE);
        const float* m1p = (const float*)(sm + MOFF + i1 * MSTRIDE);
        int c0c = (mi * 7) >> 1;        // base chunk: 0 or 3
        uint4 bb[4];
        #pragma unroll
        for (int k = 0; k < 4; k++)
            bb[k] = *(const uint4*)(bfp + (c0c + k) * 512);
        #pragma unroll
        for (int nt = 0; nt < 7; nt++) {
            int e = mi * 7 + nt;
            const uint4& B = bb[(e >> 1) - c0c];
            uint32_t u0 = (e & 1) ? B.z : B.x;
            uint32_t u1 = (e & 1) ? B.w : B.y;
            float2 bf0 = __half22float2(*reinterpret_cast<__half2*>(&u0));
            float2 bf1 = __half22float2(*reinterpret_cast<__half2*>(&u1));
            int j0 = nt * 8 + 2 * q;
            c[mi][nt][0] = c[mi][nt][0] * SCALE_F + bf0.x + m0p[j0];
            c[mi][nt][1] = c[mi][nt][1] * SCALE_F + bf0.y + m0p[j0 + 1];
            c[mi][nt][2] = c[mi][nt][2] * SCALE_F + bf1.x + m1p[j0];
            c[mi][nt][3] = c[mi][nt][3] * SCALE_F + bf1.y + m1p[j0 + 1];
        }
        float m0 = -1e30f, m1 = -1e30f;
        #pragma unroll
        for (int nt = 0; nt < 7; nt++) {
            m0 = fmaxf(m0, fmaxf(c[mi][nt][0], c[mi][nt][1]));
            m1 = fmaxf(m1, fmaxf(c[mi][nt][2], c[mi][nt][3]));
        }
        m0 = fmaxf(m0, __shfl_xor_sync(0xffffffffu, m0, 1));
        m0 = fmaxf(m0, __shfl_xor_sync(0xffffffffu, m0, 2));
        m1 = fmaxf(m1, __shfl_xor_sync(0xffffffffu, m1, 1));
        m1 = fmaxf(m1, __shfl_xor_sync(0xffffffffu, m1, 2));
        float s0 = 0.f, s1 = 0.f;
        #pragma unroll
        for (int nt = 0; nt < 7; nt++) {
            c[mi][nt][0] = __expf(c[mi][nt][0] - m0); s0 += c[mi][nt][0];
            c[mi][nt][1] = __expf(c[mi][nt][1] - m0); s0 += c[mi][nt][1];
            c[mi][nt][2] = __expf(c[mi][nt][2] - m1); s1 += c[mi][nt][2];
            c[mi][nt][3] = __expf(c[mi][nt][3] - m1); s1 += c[mi][nt][3];
        }
        s0 += __shfl_xor_sync(0xffffffffu, s0, 1);
        s0 += __shfl_xor_sync(0xffffffffu, s0, 2);
        s1 += __shfl_xor_sync(0xffffffffu, s1, 1);
        s1 += __shfl_xor_sync(0xffffffffu, s1, 2);
        inv0[mi] = 1.f / s0;
        inv1[mi] = 1.f / s1;
    }

    // ---- Pack P into fp16 A-fragments (registers only)
    uint32_t pa[2][4][4];
    #pragma unroll
    for (int mi = 0; mi < 2; mi++) {
        #pragma unroll
        for (int ch = 0; ch < 4; ch++) {
            int nt0 = 2 * ch, nt1 = 2 * ch + 1;
            pa[mi][ch][0] = pack_h2(c[mi][nt0][0] * inv0[mi], c[mi][nt0][1] * inv0[mi]);
            pa[mi][ch][1] = pack_h2(c[mi][nt0][2] * inv1[mi], c[mi][nt0][3] * inv1[mi]);
            if (nt1 < 7) {
                pa[mi][ch][2] = pack_h2(c[mi][nt1][0] * inv0[mi], c[mi][nt1][1] * inv0[mi]);
                pa[mi][ch][3] = pack_h2(c[mi][nt1][2] * inv1[mi], c[mi][nt1][3] * inv1[mi]);
            } else {
                pa[mi][ch][2] = 0u;
                pa[mi][ch][3] = 0u;
            }
        }
    }

    // ---- Phase 4: PV mma; B-frags via ldmatrix.trans on V region
    #pragma unroll
    for (int mi = 0; mi < 2; mi++) {
        int i0 = sub * 32 + mi * 16 + g;
        int i1 = i0 + 8;
        #pragma unroll
        for (int ni = 0; ni < 4; ni++) {
            float o[4] = {0.f, 0.f, 0.f, 0.f};
            #pragma unroll
            for (int hf = 0; hf < 2; hf++) {
                uint32_t addr = sbase + VOFF + (uint32_t)(hf * 32 + lane) * QKV_STRIDE
                              + hoff + ni * 16;
                uint32_t r0, r1, r2, r3;
                ldsm_x4_trans(r0, r1, r2, r3, addr);
                mma_f16(o, pa[mi][2 * hf][0], pa[mi][2 * hf][1],
                        pa[mi][2 * hf][2], pa[mi][2 * hf][3], r0, r1);
                mma_f16(o, pa[mi][2 * hf + 1][0], pa[mi][2 * hf + 1][1],
                        pa[mi][2 * hf + 1][2], pa[mi][2 * hf + 1][3], r2, r3);
            }
            int colb = (h * 32 + ni * 8) * 2 + q * 4;
            *(uint32_t*)(sm + AOOFF + i0 * AO_STRIDE + colb) = pack_h2(o[0], o[1]);
            *(uint32_t*)(sm + AOOFF + i1 * AO_STRIDE + colb) = pack_h2(o[2], o[3]);
        }
    }
    __syncthreads();

    // ---- Phase 5: proj GEMM [64x256] = AO[64x256] x W2T[256x256]^T
    const int wm   = wid & 1;
    const int wcol = wid >> 1;         // 0..7
    float d[2][4][4];
    #pragma unroll
    for (int mi = 0; mi < 2; mi++)
        #pragma unroll
        for (int ni = 0; ni < 4; ni++)
            #pragma unroll
            for (int r = 0; r < 4; r++) d[mi][ni][r] = 0.f;

    #pragma unroll
    for (int cp = 0; cp < 8; cp++) {
        uint4 ra[2], rb[2];
        #pragma unroll
        for (int mi = 0; mi < 2; mi++) {
            int r0 = wm * 32 + mi * 16 + g;
            ra[mi] = *(const uint4*)(sm + AOOFF + r0 * AO_STRIDE + cp * 64 + q * 16);
            rb[mi] = *(const uint4*)(sm + AOOFF + (r0 + 8) * AO_STRIDE + cp * 64 + q * 16);
        }
        #pragma unroll
        for (int ni = 0; ni < 4; ni++) {
            int n = wcol * 32 + ni * 8 + g;
            uint4 sb = *(const uint4*)(w2 + (size_t)n * KDIM + cp * 32 + q * 8);
            #pragma unroll
            for (int mi = 0; mi < 2; mi++) {
                mma_f16(d[mi][ni], ra[mi].x, rb[mi].x, ra[mi].y, rb[mi].y, sb.x, sb.y);
                mma_f16(d[mi][ni], ra[mi].z, rb[mi].z, ra[mi].w, rb[mi].w, sb.z, sb.w);
            }
        }
    }

    // ---- Epilogue: + proj_b, fp32 out (valid rows only)
    #pragma unroll
    for (int mi = 0; mi < 2; mi++) {
        int i0 = wm * 32 + mi * 16 + g;
        int i1 = i0 + 8;
        #pragma unroll
        for (int ni = 0; ni < 4; ni++) {
            int n0 = wcol * 32 + ni * 8 + 2 * q;
            float2 pb = *(const float2*)(proj_b + n0);
            if (i0 < NTOK) {
                float2 v = make_float2(d[mi][ni][0] + pb.x, d[mi][ni][1] + pb.y);
                *(float2*)(out + ((size_t)b * NTOK + i0) * DIM + n0) = v;
            }
            if (i1 < NTOK) {
                float2 v = make_float2(d[mi][ni][2] + pb.x, d[mi][ni][3] + pb.y);
                *(float2*)(out + ((size_t)b * NTOK + i1) * DIM + n0) = v;
            }
        }
    }
}

// ---------------------------------------------------------------------------
extern "C" void kernel_launch(void* const* d_in, const int* in_sizes, int n_in,
                              void* d_out, int out_size)
{
    const float* x      = (const float*)d_in[0];
    const float* mask   = (const float*)d_in[1];
    const float* qkv_w  = (const float*)d_in[2];
    const float* qkv_b  = (const float*)d_in[3];
    const float* rpb    = (const float*)d_in[4];
    const float* proj_w = (const float*)d_in[5];
    const float* proj_b = (const float*)d_in[6];
    float* out = (float*)d_out;

    __half *xh, *qkvh, *w1h, *w2h, *biasf;
    cudaGetSymbolAddress((void**)&xh, g_xh);
    cudaGetSymbolAddress((void**)&qkvh, g_qkvh);
    cudaGetSymbolAddress((void**)&w1h, g_w1h);
    cudaGetSymbolAddress((void**)&w2h, g_w2h);
    cudaGetSymbolAddress((void**)&biasf, g_biasf);

    cudaFuncSetAttribute(gemm_h,
                         cudaFuncAttributeMaxDynamicSharedMemorySize, GEMM_SMEM_H);
    cudaFuncSetAttribute(attn_proj_fused,
                         cudaFuncAttributeMaxDynamicSharedMemorySize, FUSE_SMEM);

    // 0) Merged pre-pass (f2h + weight transposes + bias fragment table)
    prep_kernel<<<(PREP_TOTAL + 255) / 256, 256>>>(x, xh, qkv_w, proj_w, rpb,
                                                   w1h, w2h, biasf);

    // 1) QKV GEMM (fp16)
    gemm_h<<<dim3(QKV_N / 128, MTOK / 128), 256, GEMM_SMEM_H>>>(
        xh, w1h, qkv_b, qkvh, QKV_N);

    // 2) Fused attention + projection (fp32 out)
    attn_proj_fused<<<BATCH, 512, FUSE_SMEM>>>(
        qkvh, mask, biasf, w2h, proj_b, out);
}